// round 2
// baseline (speedup 1.0000x reference)
#include <cuda_runtime.h>
#include <math.h>
#include <stdint.h>

#define DEV_INLINE __device__ __forceinline__

// ---------------- problem constants ----------------
constexpr int BB    = 8;
constexpr int NTOK  = 1024;
constexpr int IND   = 2048;
constexpr int DIM   = 512;
constexpr int NH    = 8;
constexpr int DHD   = 64;
constexpr int DEPTH = 2;
constexpr int NE    = 4;
constexpr int NC    = 10;
constexpr int SEQ   = NTOK + 1;          // 1025
constexpr int BS    = BB * SEQ;          // 8200
constexpr int M0    = BB * NTOK;         // 8192
constexpr int QD    = 3 * DIM;           // 1536
constexpr long TSZ   = (long)BS * DIM;   // per-expert activation size
constexpr long QKVSZ = (long)BS * QD;
constexpr long SS    = (long)SEQ * SEQ;

// ---------------- device scratch (static, allocation-free) ----------------
__device__ float g_R[(size_t)M0 * DIM];                    // router proj (relu)
__device__ float g_rmean[BB * DIM];
__device__ float g_gsoft[BB * NE];
__device__ float g_t[(size_t)NE * TSZ];                    // residual stream
__device__ float g_h[(size_t)NE * TSZ];                    // LN output
__device__ float g_qkv[(size_t)NE * QKVSZ];
__device__ float g_sc[(size_t)NE * BB * NH * SS];          // attention scores (~1.08 GB)
__device__ float g_ao[(size_t)NE * TSZ];                   // attention output
__device__ float g_u[(size_t)NE * TSZ];                    // MLP hidden
__device__ float g_late[NE * BB * DIM];
__device__ float g_loge[NE * BB * NC];

// ---------------- helpers ----------------
DEV_INLINE float gelu_f(float x) {
    return 0.5f * x * (1.f + tanhf(0.7978845608028654f * (x + 0.044715f * x * x * x)));
}

DEV_INLINE float block_reduce_sum(float v, float* sm) {
    #pragma unroll
    for (int o = 16; o; o >>= 1) v += __shfl_xor_sync(0xffffffffu, v, o);
    int t = threadIdx.x;
    if ((t & 31) == 0) sm[t >> 5] = v;
    __syncthreads();
    if (t < 32) {
        float z = (t < (int)(blockDim.x >> 5)) ? sm[t] : 0.f;
        #pragma unroll
        for (int o = 4; o; o >>= 1) z += __shfl_xor_sync(0xffffffffu, z, o);
        if (t == 0) sm[0] = z;
    }
    __syncthreads();
    float r = sm[0];
    __syncthreads();
    return r;
}

DEV_INLINE float block_reduce_max(float v, float* sm) {
    #pragma unroll
    for (int o = 16; o; o >>= 1) v = fmaxf(v, __shfl_xor_sync(0xffffffffu, v, o));
    int t = threadIdx.x;
    if ((t & 31) == 0) sm[t >> 5] = v;
    __syncthreads();
    if (t < 32) {
        float z = (t < (int)(blockDim.x >> 5)) ? sm[t] : -1e30f;
        #pragma unroll
        for (int o = 4; o; o >>= 1) z = fmaxf(z, __shfl_xor_sync(0xffffffffu, z, o));
        if (t == 0) sm[0] = z;
    }
    __syncthreads();
    float r = sm[0];
    __syncthreads();
    return r;
}

// ---------------- generic tiled GEMM ----------------
// C[M,Nn] = act( alpha * A[M,K] @ op(B) + bias + res )
// TRANSB: B given as [Nn,K] row-major (op = B^T). ACT: 0 none, 1 relu, 2 gelu.
// SHIFT: output row r -> r + r/1024 + 1 (token rows into [B,SEQ,DIM] with CLS slot).
template<bool TRANSB, int ACT, bool RES, bool BIAS, bool SHIFT>
DEV_INLINE void gemm_body(const float* __restrict__ A, int lda,
                          const float* __restrict__ Bm, int ldb,
                          const float* __restrict__ bias,
                          const float* res, int ldres,
                          float* Cc, int ldc,
                          int M, int Nn, int K, float alpha)
{
    constexpr int BMt = 64, BNt = 64, BKt = 16;
    __shared__ float As[BKt][BMt];
    __shared__ float Bs[BKt][BNt];
    const int tid  = threadIdx.x;                // 256 threads
    const int row0 = blockIdx.y * BMt;
    const int col0 = blockIdx.x * BNt;
    const int tr = tid >> 4, tc = tid & 15;

    float acc[4][4];
    #pragma unroll
    for (int i = 0; i < 4; i++)
        #pragma unroll
        for (int j = 0; j < 4; j++) acc[i][j] = 0.f;

    const int arow = tid >> 2;          // 0..63
    const int ak   = (tid & 3) * 4;     // 0,4,8,12
    const int bkr  = tid >> 4;          // 0..15 (opN)
    const int bcc  = (tid & 15) * 4;    // (opN)

    for (int kt = 0; kt < K; kt += BKt) {
        // --- load A tile (64 x 16), store transposed As[k][row] ---
        {
            float x0 = 0.f, x1 = 0.f, x2 = 0.f, x3 = 0.f;
            int gr = row0 + arow;
            if (gr < M) {
                const float* p = A + (long)gr * lda + kt + ak;
                int k0 = kt + ak;
                if (k0 + 0 < K) x0 = p[0];
                if (k0 + 1 < K) x1 = p[1];
                if (k0 + 2 < K) x2 = p[2];
                if (k0 + 3 < K) x3 = p[3];
            }
            As[ak + 0][arow] = x0; As[ak + 1][arow] = x1;
            As[ak + 2][arow] = x2; As[ak + 3][arow] = x3;
        }
        // --- load B tile (16 x 64) ---
        if (!TRANSB) {
            float x0 = 0.f, x1 = 0.f, x2 = 0.f, x3 = 0.f;
            int gk = kt + bkr;
            int gc = col0 + bcc;
            if (gk < K) {
                const float* p = Bm + (long)gk * ldb + gc;
                if (gc + 0 < Nn) x0 = p[0];
                if (gc + 1 < Nn) x1 = p[1];
                if (gc + 2 < Nn) x2 = p[2];
                if (gc + 3 < Nn) x3 = p[3];
            }
            Bs[bkr][bcc + 0] = x0; Bs[bkr][bcc + 1] = x1;
            Bs[bkr][bcc + 2] = x2; Bs[bkr][bcc + 3] = x3;
        } else {
            // B is [Nn,K]: Bs[k][col] = Bm[col*ldb + k]
            int col = tid >> 2;            // 0..63
            int kk  = (tid & 3) * 4;
            float x0 = 0.f, x1 = 0.f, x2 = 0.f, x3 = 0.f;
            int gc = col0 + col;
            if (gc < Nn) {
                const float* p = Bm + (long)gc * ldb + kt + kk;
                int k0 = kt + kk;
                if (k0 + 0 < K) x0 = p[0];
                if (k0 + 1 < K) x1 = p[1];
                if (k0 + 2 < K) x2 = p[2];
                if (k0 + 3 < K) x3 = p[3];
            }
            Bs[kk + 0][col] = x0; Bs[kk + 1][col] = x1;
            Bs[kk + 2][col] = x2; Bs[kk + 3][col] = x3;
        }
        __syncthreads();

        #pragma unroll
        for (int kk = 0; kk < BKt; kk++) {
            float4 a = *(const float4*)&As[kk][tr * 4];
            float4 b = *(const float4*)&Bs[kk][tc * 4];
            acc[0][0] += a.x * b.x; acc[0][1] += a.x * b.y; acc[0][2] += a.x * b.z; acc[0][3] += a.x * b.w;
            acc[1][0] += a.y * b.x; acc[1][1] += a.y * b.y; acc[1][2] += a.y * b.z; acc[1][3] += a.y * b.w;
            acc[2][0] += a.z * b.x; acc[2][1] += a.z * b.y; acc[2][2] += a.z * b.z; acc[2][3] += a.z * b.w;
            acc[3][0] += a.w * b.x; acc[3][1] += a.w * b.y; acc[3][2] += a.w * b.z; acc[3][3] += a.w * b.w;
        }
        __syncthreads();
    }

    // --- epilogue ---
    #pragma unroll
    for (int i = 0; i < 4; i++) {
        int r = row0 + tr * 4 + i;
        if (r >= M) continue;
        long orow = SHIFT ? (long)(r + r / 1024 + 1) : (long)r;
        #pragma unroll
        for (int j = 0; j < 4; j++) {
            int c = col0 + tc * 4 + j;
            if (c >= Nn) continue;
            float v = acc[i][j] * alpha;
            if (BIAS) v += bias[c];
            if (RES)  v += res[orow * ldres + c];
            if (ACT == 1) v = fmaxf(v, 0.f);
            else if (ACT == 2) v = gelu_f(v);
            Cc[orow * (long)ldc + c] = v;
        }
    }
}

// ---------------- GEMM wrappers ----------------
__global__ void __launch_bounds__(256) k_router_proj(const float* x, const float* Wr, const float* br) {
    gemm_body<false, 1, false, true, false>(x, IND, Wr, DIM, br, nullptr, 0,
                                            g_R, DIM, M0, DIM, IND, 1.f);
}

__global__ void __launch_bounds__(256) k_expert_proj(const float* x, const float* Wp, const float* bp) {
    int e = blockIdx.z;
    gemm_body<false, 1, false, true, true>(x, IND, Wp + (long)e * IND * DIM, DIM, bp + e * DIM,
                                           nullptr, 0, g_t + (long)e * TSZ, DIM, M0, DIM, IND, 1.f);
}

__global__ void __launch_bounds__(256) k_qkv(const float* Wqkv, const float* bqkv, int l) {
    int e = blockIdx.z;
    long we = (long)e * DEPTH + l;
    gemm_body<false, 0, false, true, false>(g_h + (long)e * TSZ, DIM,
                                            Wqkv + we * DIM * QD, QD, bqkv + we * QD,
                                            nullptr, 0, g_qkv + (long)e * QKVSZ, QD,
                                            BS, QD, DIM, 1.f);
}

__global__ void __launch_bounds__(256) k_scores() {
    int z = blockIdx.z;
    int e = z / (BB * NH);
    int b = (z / NH) % BB;
    int h = z % NH;
    const float* base = g_qkv + (long)e * QKVSZ + (long)b * SEQ * QD;
    gemm_body<true, 0, false, false, false>(base + h * DHD, QD,           // q
                                            base + DIM + h * DHD, QD,      // k (B^T)
                                            nullptr, nullptr, 0,
                                            g_sc + (long)z * SS, SEQ,
                                            SEQ, SEQ, DHD, 0.125f);
}

__global__ void __launch_bounds__(256) k_av() {
    int z = blockIdx.z;
    int e = z / (BB * NH);
    int b = (z / NH) % BB;
    int h = z % NH;
    gemm_body<false, 0, false, false, false>(g_sc + (long)z * SS, SEQ,
                                             g_qkv + (long)e * QKVSZ + (long)b * SEQ * QD + 2 * DIM + h * DHD, QD,
                                             nullptr, nullptr, 0,
                                             g_ao + (long)e * TSZ + (long)b * SEQ * DIM + h * DHD, DIM,
                                             SEQ, DHD, SEQ, 1.f);
}

__global__ void __launch_bounds__(256) k_oproj(const float* Wo, const float* bo, int l) {
    int e = blockIdx.z;
    long we = (long)e * DEPTH + l;
    gemm_body<false, 0, true, true, false>(g_ao + (long)e * TSZ, DIM,
                                           Wo + we * DIM * DIM, DIM, bo + we * DIM,
                                           g_t + (long)e * TSZ, DIM,
                                           g_t + (long)e * TSZ, DIM, BS, DIM, DIM, 1.f);
}

__global__ void __launch_bounds__(256) k_mlp1(const float* W1, const float* b1, int l) {
    int e = blockIdx.z;
    long we = (long)e * DEPTH + l;
    gemm_body<false, 2, false, true, false>(g_h + (long)e * TSZ, DIM,
                                            W1 + we * DIM * DIM, DIM, b1 + we * DIM,
                                            nullptr, 0, g_u + (long)e * TSZ, DIM, BS, DIM, DIM, 1.f);
}

__global__ void __launch_bounds__(256) k_mlp2(const float* W2, const float* b2, int l) {
    int e = blockIdx.z;
    long we = (long)e * DEPTH + l;
    gemm_body<false, 0, true, true, false>(g_u + (long)e * TSZ, DIM,
                                           W2 + we * DIM * DIM, DIM, b2 + we * DIM,
                                           g_t + (long)e * TSZ, DIM,
                                           g_t + (long)e * TSZ, DIM, BS, DIM, DIM, 1.f);
}

// ---------------- non-GEMM kernels ----------------
__global__ void __launch_bounds__(512) k_set_cls(const float* cls) {
    int b = blockIdx.x, e = blockIdx.y;
    g_t[(size_t)e * TSZ + (size_t)b * SEQ * DIM + threadIdx.x] = cls[e * DIM + threadIdx.x];
}

// LayerNorm: fin==0: rows of g_t -> g_h (grid BS x NE); fin==1: CLS rows -> g_late (grid BB x NE)
__global__ void __launch_bounds__(256) k_ln(const float* g, const float* bb, long gE, int fin) {
    __shared__ float sm[8];
    int e = blockIdx.y;
    const float* xp;
    float* op;
    if (fin == 0) {
        long row = blockIdx.x;
        xp = g_t + (long)e * TSZ + row * DIM;
        op = g_h + (long)e * TSZ + row * DIM;
    } else {
        int b = blockIdx.x;
        xp = g_t + (long)e * TSZ + (long)b * SEQ * DIM;
        op = g_late + ((long)e * BB + b) * DIM;
    }
    const float* gp = g + e * gE;
    const float* bp = bb + e * gE;
    int t = threadIdx.x;
    float x0 = xp[t], x1 = xp[t + 256];
    float s  = block_reduce_sum(x0 + x1, sm);
    float sq = block_reduce_sum(x0 * x0 + x1 * x1, sm);
    float m = s * (1.f / DIM);
    float v = sq * (1.f / DIM) - m * m;
    float inv = rsqrtf(v + 1e-5f);
    op[t]       = (x0 - m) * inv * gp[t]       + bp[t];
    op[t + 256] = (x1 - m) * inv * gp[t + 256] + bp[t + 256];
}

__global__ void __launch_bounds__(256) k_softmax() {
    __shared__ float sm[8];
    int e = blockIdx.y;
    long row = blockIdx.x;
    float* p = g_sc + (long)e * (BB * NH * SS) + row * SEQ;
    int t = threadIdx.x;
    float v[5];
    float mx = -1e30f;
    #pragma unroll
    for (int i = 0; i < 5; i++) {
        int idx = t + i * 256;
        v[i] = (idx < SEQ) ? p[idx] : -1e30f;
        mx = fmaxf(mx, v[i]);
    }
    mx = block_reduce_max(mx, sm);
    float s = 0.f;
    #pragma unroll
    for (int i = 0; i < 5; i++) {
        int idx = t + i * 256;
        if (idx < SEQ) { v[i] = __expf(v[i] - mx); s += v[i]; } else v[i] = 0.f;
    }
    s = block_reduce_sum(s, sm);
    float inv = 1.f / s;
    #pragma unroll
    for (int i = 0; i < 5; i++) {
        int idx = t + i * 256;
        if (idx < SEQ) p[idx] = v[i] * inv;
    }
}

__global__ void __launch_bounds__(512) k_meanpool() {
    int b = blockIdx.x, d = threadIdx.x;
    const float* p = g_R + (long)b * NTOK * DIM + d;
    float s = 0.f;
    for (int n = 0; n < NTOK; n++) s += p[(long)n * DIM];
    g_rmean[b * DIM + d] = s * (1.f / NTOK);
}

__global__ void __launch_bounds__(32) k_router_head(const float* Wrf, const float* brf) {
    __shared__ float lg[BB][NE];
    int t = threadIdx.x;
    if (t < BB * NE) {
        int b = t / NE, e = t % NE;
        float s = brf[e];
        for (int d = 0; d < DIM; d++) s += g_rmean[b * DIM + d] * Wrf[d * NE + e];
        lg[b][e] = s;
    }
    __syncthreads();
    if (t < BB) {
        float mx = -1e30f;
        for (int e = 0; e < NE; e++) mx = fmaxf(mx, lg[t][e]);
        float ex[NE], sum = 0.f;
        for (int e = 0; e < NE; e++) { ex[e] = __expf(lg[t][e] - mx); sum += ex[e]; }
        for (int e = 0; e < NE; e++) g_gsoft[t * NE + e] = ex[e] / sum;
    }
}

__global__ void __launch_bounds__(320) k_head(const float* Wh, const float* bh) {
    int eb = blockIdx.x;
    int e = eb / BB;
    int w = threadIdx.x >> 5, lane = threadIdx.x & 31;  // w in [0,10)
    const float* lat = g_late + (long)eb * DIM;
    const float* wp  = Wh + (long)e * DIM * NC;
    float s = 0.f;
    for (int d = lane; d < DIM; d += 32) s += lat[d] * wp[d * NC + w];
    #pragma unroll
    for (int o = 16; o; o >>= 1) s += __shfl_xor_sync(0xffffffffu, s, o);
    if (lane == 0) g_loge[eb * NC + w] = s + bh[e * NC + w];
}

__global__ void __launch_bounds__(256) k_combine(float* out, int out_size) {
    int idx = blockIdx.x * 256 + threadIdx.x;
    if (idx >= out_size) return;
    if (idx < BB * DIM) {
        int b = idx / DIM, d = idx % DIM;
        float s = 0.f;
        for (int e = 0; e < NE; e++) s += g_gsoft[b * NE + e] * g_late[(e * BB + b) * DIM + d];
        out[idx] = s;
    } else if (idx < BB * DIM + BB * NC) {
        int i = idx - BB * DIM;
        int b = i / NC, c = i % NC;
        float s = 0.f;
        for (int e = 0; e < NE; e++) s += g_gsoft[b * NE + e] * g_loge[(e * BB + b) * NC + c];
        out[idx] = s;
    } else if (idx < BB * DIM + BB * NC + BB * NE) {
        out[idx] = g_gsoft[idx - BB * DIM - BB * NC];
    } else {
        out[idx] = 0.f;
    }
}

// ---------------- launch ----------------
extern "C" void kernel_launch(void* const* d_in, const int* in_sizes, int n_in,
                              void* d_out, int out_size) {
    const float* x    = (const float*)d_in[0];
    const float* Wr   = (const float*)d_in[1];
    const float* br   = (const float*)d_in[2];
    const float* Wrf  = (const float*)d_in[3];
    const float* brf  = (const float*)d_in[4];
    const float* Wp   = (const float*)d_in[5];
    const float* bp   = (const float*)d_in[6];
    const float* cls  = (const float*)d_in[7];
    const float* ln1g = (const float*)d_in[8];
    const float* ln1b = (const float*)d_in[9];
    const float* Wqkv = (const float*)d_in[10];
    const float* bqkv = (const float*)d_in[11];
    const float* Wo   = (const float*)d_in[12];
    const float* bo   = (const float*)d_in[13];
    const float* ln2g = (const float*)d_in[14];
    const float* ln2b = (const float*)d_in[15];
    const float* W1   = (const float*)d_in[16];
    const float* b1   = (const float*)d_in[17];
    const float* W2   = (const float*)d_in[18];
    const float* b2   = (const float*)d_in[19];
    const float* lnfg = (const float*)d_in[20];
    const float* lnfb = (const float*)d_in[21];
    const float* Wh   = (const float*)d_in[22];
    const float* bh   = (const float*)d_in[23];
    float* out = (float*)d_out;

    dim3 blk(256);
    const int gyBS = (BS + 63) / 64;   // 129
    const int gyM0 = M0 / 64;          // 128
    const int gyS  = (SEQ + 63) / 64;  // 17

    // router path
    k_router_proj<<<dim3(DIM / 64, gyM0), blk>>>(x, Wr, br);
    k_meanpool<<<BB, DIM>>>();
    k_router_head<<<1, 32>>>(Wrf, brf);

    // expert input projection + CLS token
    k_expert_proj<<<dim3(DIM / 64, gyM0, NE), blk>>>(x, Wp, bp);
    k_set_cls<<<dim3(BB, NE), DIM>>>(cls);

    for (int l = 0; l < DEPTH; l++) {
        k_ln<<<dim3(BS, NE), 256>>>(ln1g + l * DIM, ln1b + l * DIM, (long)DEPTH * DIM, 0);
        k_qkv<<<dim3(QD / 64, gyBS, NE), blk>>>(Wqkv, bqkv, l);
        k_scores<<<dim3(gyS, gyS, NE * BB * NH), blk>>>();
        k_softmax<<<dim3(BB * NH * SEQ, NE), 256>>>();
        k_av<<<dim3(1, gyS, NE * BB * NH), blk>>>();
        k_oproj<<<dim3(DIM / 64, gyBS, NE), blk>>>(Wo, bo, l);
        k_ln<<<dim3(BS, NE), 256>>>(ln2g + l * DIM, ln2b + l * DIM, (long)DEPTH * DIM, 0);
        k_mlp1<<<dim3(DIM / 64, gyBS, NE), blk>>>(W1, b1, l);
        k_mlp2<<<dim3(DIM / 64, gyBS, NE), blk>>>(W2, b2, l);
    }

    k_ln<<<dim3(BB, NE), 256>>>(lnfg, lnfb, (long)DIM, 1);
    k_head<<<NE * BB, 320>>>(Wh, bh);
    k_combine<<<(out_size + 255) / 256, 256>>>(out, out_size);
}